// round 9
// baseline (speedup 1.0000x reference)
#include <cuda_runtime.h>
#include <math.h>
#include <stdint.h>

typedef unsigned long long u64;

// ---------------- scratch (static device globals; no allocation) -------------
__device__ float g_h1[256 * 32 * 30 * 30];   // conv1 output (relu'd)
__device__ float g_w2t[64 * 32 * 9];         // conv2 weights transposed [c][k][oc]
__device__ float g_h3[256 * 12544];          // conv2+pool output, flattened
__device__ float g_fc1[256 * 128];           // fc1 raw accumulator (pre-bias)
__device__ float g_z[256 * 48];              // backbone output
__device__ float g_dsel[256 * 48];           // class-sorted diffs (z - center[cls])
__device__ float g_cwn[10];                  // class weight / 256
__device__ int   g_seg[11];                  // class segment offsets into g_dsel

#define NPAIR 1176            // 48*49/2
#define NTRI  19600           // C(50,3)
#define NQUAD 249900          // C(51,4)
#define TRILEN 692076         // 1176*1177/2

__device__ float g_C[10 * TRILEN];           // per-class pair-pair products
__device__ int   g_qtri[NQUAD];
__device__ float g_qw[NQUAD];
__device__ float g_qt4[NQUAD];
__device__ unsigned short g_pij[NPAIR];

// ---------------- helpers ----------------------------------------------------
__device__ __forceinline__ float sgn_of(float m) { return (m < 0.f) ? -1.f : 1.f; }

__device__ __forceinline__ float sqapx(float x) {
    float y; asm("sqrt.approx.f32 %0, %1;" : "=f"(y) : "f"(x)); return y;
}
__device__ __forceinline__ float lg2apx(float x) {
    float y; asm("lg2.approx.f32 %0, %1;" : "=f"(y) : "f"(x)); return y;
}
__device__ __forceinline__ float ex2apx(float x) {
    float y; asm("ex2.approx.f32 %0, %1;" : "=f"(y) : "f"(x)); return y;
}
__device__ __forceinline__ float sr2a(float m) {
    return sgn_of(m) * (sqapx(fabsf(m) + 0.25f) - 0.5f);
}
__device__ __forceinline__ float sr3a(float m) {
    float x = fabsf(m) + 0.19245008973f;
    float r = ex2apx(lg2apx(x) * 0.3333333333f);
    return sgn_of(m) * (r - 0.57735026919f);
}
__device__ __forceinline__ float sr4a(float m) {
    return sgn_of(m) * (sqapx(sqapx(fabsf(m) + 0.15749013123f)) - 0.62996052494f);
}

__device__ __forceinline__ void decode_pair(int pi, int& i, int& j) {
    int ii = 0, rem = pi;
    while (rem >= 48 - ii) { rem -= 48 - ii; ii++; }
    i = ii; j = ii + rem;
}
__device__ __forceinline__ int pidx(int i, int j) {   // i<=j
    return i * 48 - (i * (i - 1)) / 2 + (j - i);
}

__device__ __forceinline__ float block_reduce_256(float v, float* red) {
    int tid = threadIdx.x;
    red[tid] = v; __syncthreads();
    for (int s = 128; s > 0; s >>= 1) {
        if (tid < s) red[tid] += red[tid + s];
        __syncthreads();
    }
    return red[0];
}

__device__ __forceinline__ u64 pk2(float lo, float hi) {
    u64 r; asm("mov.b64 %0, {%1, %2};" : "=l"(r) : "f"(lo), "f"(hi)); return r;
}
__device__ __forceinline__ void upk2(float& lo, float& hi, u64 v) {
    asm("mov.b64 {%0, %1}, %2;" : "=f"(lo), "=f"(hi) : "l"(v));
}
#define FMA2(d, a, b) asm("fma.rn.f32x2 %0, %1, %2, %0;" : "+l"(d) : "l"(a), "l"(b))

// ---------------- 0a: zero + w2 transpose + pair table -----------------------
__global__ void zero_k(float* __restrict__ out, const float* __restrict__ w2) {
    int i = blockIdx.x * 256 + threadIdx.x;
    if (i < 256 * 128) g_fc1[i] = 0.f;
    if (i < 4) out[2560 + i] = 0.f;
    if (i < 18432) {
        // dst [(c*9+k)*64 + oc] = src [oc*288 + c*9 + k]
        int oc = i / 288, rem = i - oc * 288;
        g_w2t[rem * 64 + oc] = w2[i];
    }
    if (i < NPAIR) {
        int a, b; decode_pair(i, a, b);
        g_pij[i] = (unsigned short)((a << 8) | b);
    }
}

// ---------------- 0b: quad list ----------------------------------------------
__global__ void quad_k(const float* __restrict__ mw, const float* __restrict__ gm4) {
    int e = blockIdx.x * 256 + threadIdx.x;
    if (e >= NQUAD) return;
    int r = e, a = 0, b = 0, c = 0, d;
    for (a = 0; a < 48; a++) { int n = 50 - a; int cnt = n * (n - 1) * (n - 2) / 6; if (r < cnt) break; r -= cnt; }
    for (b = a; b < 48; b++) { int n = 49 - b; int cnt = n * (n - 1) / 2; if (r < cnt) break; r -= cnt; }
    for (c = b; c < 48; c++) { int cnt = 48 - c; if (r < cnt) break; r -= cnt; }
    d = c + r;
    bool ab = (a == b), bc = (b == c), cd = (c == d);
    int perm;
    if (ab && bc && cd) perm = 1;
    else if ((ab && bc) || (bc && cd)) perm = 4;
    else if (ab && cd) perm = 6;
    else if (ab || bc || cd) perm = 12;
    else perm = 24;
    g_qw[e] = 0.25f * (float)perm * (mw[a] + mw[b] + mw[c] + mw[d]);
    int p = pidx(a, b), q = pidx(c, d);
    g_qtri[e] = p * 1176 - (p * (p - 1)) / 2 + (q - p);
    g_qt4[e] = sr4a(gm4[(((a * 48 + b) * 48) + c) * 48 + d]);
}

// ---------------- 1: conv1 (3->32, 3x3 valid, relu), sliding 3-col window ----
__global__ __launch_bounds__(256) void conv1_k(const float* __restrict__ x,
                                               const float* __restrict__ w,
                                               const float* __restrict__ bias) {
    __shared__ float xs[3 * 32 * 32];
    __shared__ float ws[32 * 27];
    __shared__ float bs[32];
    int b = blockIdx.x, tid = threadIdx.x;
    for (int i = tid; i < 3072; i += 256) xs[i] = x[b * 3072 + i];
    for (int i = tid; i < 864; i += 256) ws[i] = w[i];
    if (tid < 32) bs[tid] = bias[tid];
    __syncthreads();

    int oc = tid >> 3, ys = tid & 7;
    float wr[3][3][3];
#pragma unroll
    for (int c = 0; c < 3; c++)
#pragma unroll
        for (int ky = 0; ky < 3; ky++)
#pragma unroll
            for (int kx = 0; kx < 3; kx++)
                wr[c][ky][kx] = ws[oc * 27 + c * 9 + ky * 3 + kx];
    float bv = bs[oc];

    for (int y = ys; y < 30; y += 8) {
        float win[3][3][3];
#pragma unroll
        for (int c = 0; c < 3; c++)
#pragma unroll
            for (int ky = 0; ky < 3; ky++) {
                win[c][ky][0] = xs[c * 1024 + (y + ky) * 32 + 0];
                win[c][ky][1] = xs[c * 1024 + (y + ky) * 32 + 1];
            }
        float* orow = &g_h1[((b * 32 + oc) * 30 + y) * 30];
#pragma unroll
        for (int xc = 0; xc < 30; xc++) {
            int s2 = (xc + 2) % 3;
#pragma unroll
            for (int c = 0; c < 3; c++)
#pragma unroll
                for (int ky = 0; ky < 3; ky++)
                    win[c][ky][s2] = xs[c * 1024 + (y + ky) * 32 + xc + 2];
            float acc = bv;
#pragma unroll
            for (int c = 0; c < 3; c++)
#pragma unroll
                for (int ky = 0; ky < 3; ky++)
#pragma unroll
                    for (int kx = 0; kx < 3; kx++)
                        acc = fmaf(win[c][ky][(xc + kx) % 3], wr[c][ky][kx], acc);
            orow[xc] = fmaxf(acc, 0.f);
        }
    }
}

// ---------------- 2: conv2 + bias + relu + maxpool; oc-pair f32x2 (R6) -------
// grid (2 oc-halves, 256 images), 224 threads = 2 prh x 14 col x 8 ocq(4 oc).
__global__ __launch_bounds__(224, 3) void conv2_k(const float* __restrict__ bias) {
    extern __shared__ float sm[];
    float* wsh = sm;            // 32oc x 32c x 9k as [c][k][oc32] = 9216 floats
    float2* insh2 = (float2*)(sm + 9216);   // reuse as scalar region below
    float* insh = sm + 9216;    // 32c x 6r x 30 = 5760 floats
    __shared__ float bs[32];
    int oh = blockIdx.x, b = blockIdx.y, tid = threadIdx.x;
    (void)insh2;

    {   // weights: dst f4 i <- src f4 [(i>>3)*16 + oh*8 + (i&7)]
        float4* wd = (float4*)wsh;
        const float4* wsrc = (const float4*)g_w2t;
        for (int i = tid; i < 2304; i += 224)
            wd[i] = wsrc[(i >> 3) * 16 + oh * 8 + (i & 7)];
        if (tid < 32) bs[tid] = bias[oh * 32 + tid];
    }

    int prh = tid / 112, rem = tid % 112, col = rem / 8, ocq = rem & 7;

    for (int it = 0; it < 7; it++) {
        __syncthreads();
        for (int i = tid; i < 5760; i += 224) {
            int c = i / 180, r2 = i - c * 180;
            int r = r2 / 30, cc = r2 - r * 30;
            insh[i] = g_h1[((b * 32 + c) * 30 + 4 * it + r) * 30 + cc];
        }
        __syncthreads();

        u64 acc2[2][4];   // [oc pair][pool dy*2+dx]
#pragma unroll
        for (int p2 = 0; p2 < 2; p2++)
#pragma unroll
            for (int p = 0; p < 4; p++) acc2[p2][p] = 0ull;

        for (int c = 0; c < 32; c++) {
            const float* ip = insh + c * 180 + prh * 60 + col * 2;
            u64 ipk[4][4];
#pragma unroll
            for (int rr = 0; rr < 4; rr++) {
                float2 v0 = *(const float2*)&ip[rr * 30];
                float2 v1 = *(const float2*)&ip[rr * 30 + 2];
                ipk[rr][0] = pk2(v0.x, v0.x);
                ipk[rr][1] = pk2(v0.y, v0.y);
                ipk[rr][2] = pk2(v1.x, v1.x);
                ipk[rr][3] = pk2(v1.y, v1.y);
            }
#pragma unroll
            for (int kk = 0; kk < 9; kk++) {
                int wb = (c * 9 + kk) * 32 + ocq * 4;
                ulonglong2 wp = *(const ulonglong2*)&wsh[wb];   // two packed oc-pairs
                int ky = kk / 3, kx = kk - ky * 3;
#pragma unroll
                for (int dy = 0; dy < 2; dy++)
#pragma unroll
                    for (int dx = 0; dx < 2; dx++) {
                        u64 iv = ipk[dy + ky][dx + kx];
                        FMA2(acc2[0][dy * 2 + dx], wp.x, iv);
                        FMA2(acc2[1][dy * 2 + dx], wp.y, iv);
                    }
            }
        }

        int pr = 2 * it + prh;
#pragma unroll
        for (int p2 = 0; p2 < 2; p2++) {
            float l0, h0, l1, h1, l2, h2, l3, h3;
            upk2(l0, h0, acc2[p2][0]); upk2(l1, h1, acc2[p2][1]);
            upk2(l2, h2, acc2[p2][2]); upk2(l3, h3, acc2[p2][3]);
            float mlo = fmaxf(fmaxf(l0, l1), fmaxf(l2, l3));
            float mhi = fmaxf(fmaxf(h0, h1), fmaxf(h2, h3));
            int ocl = ocq * 4 + p2 * 2;
            int ocg = oh * 32 + ocl;
            g_h3[b * 12544 + ocg * 196 + pr * 14 + col] = fmaxf(mlo + bs[ocl], 0.f);
            g_h3[b * 12544 + (ocg + 1) * 196 + pr * 14 + col] = fmaxf(mhi + bs[ocl + 1], 0.f);
        }
    }
}

// ---------------- 3: fc1 GEMM split-K, 4x4 BN=64, 98 K-splits of 128 ---------
__global__ void fc1_k(const float* __restrict__ w1) {
    __shared__ __align__(16) float As[32][64];
    __shared__ __align__(16) float Ws[32][64];
    int mt = blockIdx.x, nt = blockIdx.y, s = blockIdx.z, tid = threadIdx.x;
    int m0 = mt * 64, n0 = nt * 64;
    float acc[4][4];
#pragma unroll
    for (int u = 0; u < 4; u++)
#pragma unroll
        for (int v = 0; v < 4; v++) acc[u][v] = 0.f;

    int row = tid / 8, kc = (tid % 8) * 4;
    int tr = tid / 16, tc = tid % 16;

    for (int kt = 0; kt < 4; kt++) {
        int k0 = s * 128 + kt * 32;
#pragma unroll
        for (int h = 0; h < 2; h++) {
            float4 va = *(const float4*)&g_h3[(size_t)(m0 + row + 32 * h) * 12544 + k0 + kc];
            As[kc + 0][row + 32 * h] = va.x; As[kc + 1][row + 32 * h] = va.y;
            As[kc + 2][row + 32 * h] = va.z; As[kc + 3][row + 32 * h] = va.w;
            float4 vw = *(const float4*)&w1[(size_t)(n0 + row + 32 * h) * 12544 + k0 + kc];
            Ws[kc + 0][row + 32 * h] = vw.x; Ws[kc + 1][row + 32 * h] = vw.y;
            Ws[kc + 2][row + 32 * h] = vw.z; Ws[kc + 3][row + 32 * h] = vw.w;
        }
        __syncthreads();
#pragma unroll
        for (int kk = 0; kk < 32; kk++) {
            float4 a = *(const float4*)&As[kk][tr * 4];
            float4 wv = *(const float4*)&Ws[kk][tc * 4];
            float av[4] = {a.x, a.y, a.z, a.w};
            float wvv[4] = {wv.x, wv.y, wv.z, wv.w};
#pragma unroll
            for (int u = 0; u < 4; u++)
#pragma unroll
                for (int v = 0; v < 4; v++) acc[u][v] = fmaf(av[u], wvv[v], acc[u][v]);
        }
        __syncthreads();
    }
#pragma unroll
    for (int u = 0; u < 4; u++)
#pragma unroll
        for (int v = 0; v < 4; v++)
            atomicAdd(&g_fc1[(m0 + tr * 4 + u) * 128 + n0 + tc * 4 + v], acc[u][v]);
}

// ---------------- 4: bias+relu, fc2 (relu), fc3 -> z; smem-staged weights ----
__global__ void fc23_k(const float* __restrict__ b1, const float* __restrict__ w2,
                       const float* __restrict__ b2, const float* __restrict__ w3,
                       const float* __restrict__ b3) {
    extern __shared__ float smw[];
    float* w2s = smw;            // [k][o] pitch 129
    float* w3s = smw + 16512;    // [k][o] pitch 48
    __shared__ float s1[128], s2[128];
    int b = blockIdx.x, tid = threadIdx.x;

    for (int i4 = tid; i4 < 4096; i4 += 128) {
        float4 v = ((const float4*)w2)[i4];
        int o = (i4 * 4) / 128, k = (i4 * 4) % 128;
        w2s[(k + 0) * 129 + o] = v.x;
        w2s[(k + 1) * 129 + o] = v.y;
        w2s[(k + 2) * 129 + o] = v.z;
        w2s[(k + 3) * 129 + o] = v.w;
    }
    for (int i4 = tid; i4 < 1536; i4 += 128) {
        float4 v = ((const float4*)w3)[i4];
        int o = (i4 * 4) / 128, k = (i4 * 4) % 128;
        w3s[(k + 0) * 48 + o] = v.x;
        w3s[(k + 1) * 48 + o] = v.y;
        w3s[(k + 2) * 48 + o] = v.z;
        w3s[(k + 3) * 48 + o] = v.w;
    }
    s1[tid] = fmaxf(g_fc1[b * 128 + tid] + b1[tid], 0.f);
    __syncthreads();

    float acc = b2[tid];
    for (int k = 0; k < 128; k++) acc = fmaf(w2s[k * 129 + tid], s1[k], acc);
    s2[tid] = fmaxf(acc, 0.f);
    __syncthreads();
    if (tid < 48) {
        float a = b3[tid];
        for (int k = 0; k < 128; k++) a = fmaf(w3s[k * 48 + tid], s2[k], a);
        g_z[b * 48 + tid] = a;
    }
}

// ---------------- 5: distances, log-softmax, argmin, class sort --------------
__global__ void prep_k(const float* __restrict__ centers, float* __restrict__ out) {
    __shared__ float cs[480];
    __shared__ int counts[10], segs[11], cursor[10];
    int tid = threadIdx.x;
    for (int i = tid; i < 480; i += 256) cs[i] = centers[i];
    if (tid < 10) { counts[tid] = 0; cursor[tid] = 0; }
    __syncthreads();

    float zr[48];
#pragma unroll
    for (int i = 0; i < 48; i++) zr[i] = g_z[tid * 48 + i];

    float dist[10];
    int best = 0; float bd = 3.4e38f;
#pragma unroll
    for (int c = 0; c < 10; c++) {
        float d = 0.f;
#pragma unroll
        for (int i = 0; i < 48; i++) {
            float t = zr[i] - cs[c * 48 + i];
            d = fmaf(t, t, d);
        }
        dist[c] = d;
        if (d < bd) { bd = d; best = c; }
    }
    float mx = -3.4e38f;
#pragma unroll
    for (int c = 0; c < 10; c++) mx = fmaxf(mx, -0.5f * dist[c]);
    float se = 0.f;
#pragma unroll
    for (int c = 0; c < 10; c++) se += expf(-0.5f * dist[c] - mx);
    float lse = logf(se);
    float lclip = logf(1e-8f);
#pragma unroll
    for (int c = 0; c < 10; c++)
        out[tid * 10 + c] = fmaxf(-0.5f * dist[c] - mx - lse, lclip);

    atomicAdd(&counts[best], 1);
    __syncthreads();
    if (tid == 0) {
        segs[0] = 0;
        for (int c = 0; c < 10; c++) segs[c + 1] = segs[c] + counts[c];
    }
    __syncthreads();
    int pos = segs[best] + atomicAdd(&cursor[best], 1);
#pragma unroll
    for (int i = 0; i < 48; i++) g_dsel[pos * 48 + i] = zr[i] - cs[best * 48 + i];
    if (tid < 10) g_cwn[tid] = (float)counts[tid] * (1.f / 256.f);
    if (tid < 11) g_seg[tid] = segs[tid];
}

// ---------------- 6: p1 + p2 (per class, segment staged in smem) -------------
__global__ void m12_k(const float* __restrict__ mw, const float* __restrict__ gm1,
                      const float* __restrict__ gm2, float* __restrict__ out) {
    extern __shared__ float dss[];   // seg x 48
    __shared__ float red[256];
    int c = blockIdx.x, tid = threadIdx.x;
    int s0 = g_seg[c], s1 = g_seg[c + 1];
    int rows = s1 - s0;
    float cwf = (float)rows;
    float denom = cwf + 1e-7f;
    float cwn = cwf * (1.f / 256.f);

    for (int i = tid; i < rows * 12; i += 256)
        ((float4*)dss)[i] = ((const float4*)(g_dsel + s0 * 48))[i];
    __syncthreads();

    if (tid < 48) {
        float s = 0.f;
        for (int t = 0; t < rows; t++) s += dss[t * 48 + tid];
        float m1 = s / denom;
        float d = m1 - gm1[tid];
        atomicAdd(&out[2560], cwn * mw[tid] * d * d);
    }
    float part = 0.f;
    for (int e = tid; e < 2304; e += 256) {
        int i = e / 48, j = e % 48;
        float s = 0.f;
        for (int t = 0; t < rows; t++) s = fmaf(dss[t * 48 + i], dss[t * 48 + j], s);
        float v = sr2a(s / denom) - sr2a(gm2[e]);
        part += cwn * mw[j] * v * v;
    }
    float tot = block_reduce_256(part, red);
    if (tid == 0) atomicAdd(&out[2561], tot);
}

// ---------------- 7: p3 via sorted triples (full symmetry) -------------------
__global__ void p3_k(const float* __restrict__ mw, const float* __restrict__ gm3,
                     float* __restrict__ out) {
    extern __shared__ float ds[];   // 256*48
    __shared__ float cwnS[10];
    __shared__ int segS[11];
    __shared__ float red[256];
    int tid = threadIdx.x;
    for (int i = tid; i < 3072; i += 256) ((float4*)ds)[i] = ((const float4*)g_dsel)[i];
    if (tid < 10) cwnS[tid] = g_cwn[tid];
    if (tid < 11) segS[tid] = g_seg[tid];
    __syncthreads();

    int e = blockIdx.x * 256 + tid;
    float part = 0.f;
    if (e < NTRI) {
        int r = e, a = 0, b = 0, c3;
        for (a = 0; a < 48; a++) { int n = 49 - a; int cnt = n * (n - 1) / 2; if (r < cnt) break; r -= cnt; }
        for (b = a; b < 48; b++) { int cnt = 48 - b; if (r < cnt) break; r -= cnt; }
        c3 = b + r;
        bool ab = (a == b), bc = (b == c3);
        int perm = (ab && bc) ? 1 : ((ab || bc) ? 3 : 6);
        float wgt = (float)perm * (1.f / 3.f) * (mw[a] + mw[b] + mw[c3]);
        float t3 = sr3a(gm3[((a * 48 + b) * 48) + c3]);
        for (int c = 0; c < 10; c++) {
            float acc = 0.f;
            for (int t = segS[c]; t < segS[c + 1]; t++) {
                const float* d = ds + t * 48;
                acc = fmaf(d[a] * d[b], d[c3], acc);
            }
            float v = sr3a(acc) - t3;
            part += cwnS[c] * wgt * v * v;
        }
    }
    float tot = block_reduce_256(part, red);
    if (tid == 0) atomicAdd(&out[2562], tot);
}

// ---------------- 8a: pair-product GEMM C = P^T P per class ------------------
__global__ void p4a_k() {
    extern __shared__ float sm[];
    float* dsS = sm;             // up to 256*48
    float* As  = sm + 12288;     // 32*64
    float* Bs  = sm + 12288 + 2048;
    __shared__ unsigned short pijS[NPAIR];
    int tid = threadIdx.x;
    int c = blockIdx.y;
    int seg0 = g_seg[c], seg1 = g_seg[c + 1];
    int rows = seg1 - seg0;
    if (rows == 0) return;

    int tt = blockIdx.x, tp = 0;
    { int r = tt; for (tp = 0; tp < 19; tp++) { int n = 19 - tp; if (r < n) break; r -= n; } tt = r; }
    int tq = tp + tt;
    int p0 = tp * 64, q0 = tq * 64;

    for (int i = tid; i < NPAIR; i += 256) pijS[i] = g_pij[i];
    for (int i = tid; i < rows * 12; i += 256)
        ((float4*)dsS)[i] = ((const float4*)(g_dsel + seg0 * 48))[i];
    __syncthreads();

    int tr = tid >> 4, tc = tid & 15;
    float acc[4][4];
#pragma unroll
    for (int u = 0; u < 4; u++)
#pragma unroll
        for (int v = 0; v < 4; v++) acc[u][v] = 0.f;

    for (int tbase = 0; tbase < rows; tbase += 32) {
        for (int s = tid; s < 4096; s += 256) {
            int mtx = s >> 11, ss = s & 2047;
            int kkk = ss >> 6, pp = ss & 63;
            int p = (mtx ? q0 : p0) + pp;
            float v = 0.f;
            int t = tbase + kkk;
            if (p < NPAIR && t < rows) {
                int ij = pijS[p];
                v = dsS[t * 48 + (ij >> 8)] * dsS[t * 48 + (ij & 255)];
            }
            (mtx ? Bs : As)[ss] = v;
        }
        __syncthreads();
#pragma unroll
        for (int kkk = 0; kkk < 32; kkk++) {
            float4 a = *(const float4*)&As[kkk * 64 + tr * 4];
            float4 bv = *(const float4*)&Bs[kkk * 64 + tc * 4];
            float av[4] = {a.x, a.y, a.z, a.w};
            float bvv[4] = {bv.x, bv.y, bv.z, bv.w};
#pragma unroll
            for (int u = 0; u < 4; u++)
#pragma unroll
                for (int v = 0; v < 4; v++) acc[u][v] = fmaf(av[u], bvv[v], acc[u][v]);
        }
        __syncthreads();
    }

    float* Cc = g_C + (size_t)c * TRILEN;
#pragma unroll
    for (int u = 0; u < 4; u++) {
        int p = p0 + tr * 4 + u;
        if (p >= NPAIR) continue;
        int rowoff = p * 1176 - (p * (p - 1)) / 2 - p;
#pragma unroll
        for (int v = 0; v < 4; v++) {
            int q = q0 + tc * 4 + v;
            if (q < NPAIR && p <= q) Cc[rowoff + q] = acc[u][v];
        }
    }
}

// ---------------- 8b: p4 reduce over sorted quads ----------------------------
__global__ void p4b_k(float* __restrict__ out) {
    __shared__ float red[256];
    __shared__ float cw[10];
    int tid = threadIdx.x;
    if (tid < 10) cw[tid] = g_cwn[tid];
    __syncthreads();
    int e = blockIdx.x * 256 + tid;
    float part = 0.f;
    if (e < NQUAD) {
        int tri = g_qtri[e];
        float w = g_qw[e], t4 = g_qt4[e];
#pragma unroll
        for (int c = 0; c < 10; c++) {
            float cc = cw[c];
            if (cc <= 0.f) continue;
            float v = sr4a(g_C[(size_t)c * TRILEN + tri]) - t4;
            part += cc * w * v * v;
        }
    }
    float tot = block_reduce_256(part, red);
    if (tid == 0) atomicAdd(&out[2563], tot);
}

// ---------------- launch -----------------------------------------------------
extern "C" void kernel_launch(void* const* d_in, const int* in_sizes, int n_in,
                              void* d_out, int out_size) {
    const float* x    = (const float*)d_in[0];
    const float* c1w  = (const float*)d_in[1];
    const float* c1b  = (const float*)d_in[2];
    const float* c2w  = (const float*)d_in[3];
    const float* c2b  = (const float*)d_in[4];
    const float* f1w  = (const float*)d_in[5];
    const float* f1b  = (const float*)d_in[6];
    const float* f2w  = (const float*)d_in[7];
    const float* f2b  = (const float*)d_in[8];
    const float* f3w  = (const float*)d_in[9];
    const float* f3b  = (const float*)d_in[10];
    const float* cen  = (const float*)d_in[11];
    const float* mw   = (const float*)d_in[12];
    const float* gm1  = (const float*)d_in[13];
    const float* gm2  = (const float*)d_in[14];
    const float* gm3  = (const float*)d_in[15];
    const float* gm4  = (const float*)d_in[16];
    float* out = (float*)d_out;

    cudaFuncSetAttribute(conv2_k, cudaFuncAttributeMaxDynamicSharedMemorySize, 59904);
    cudaFuncSetAttribute(fc23_k, cudaFuncAttributeMaxDynamicSharedMemorySize, 90624);
    cudaFuncSetAttribute(p4a_k, cudaFuncAttributeMaxDynamicSharedMemorySize, 65536);
    cudaFuncSetAttribute(p3_k, cudaFuncAttributeMaxDynamicSharedMemorySize, 49152);
    cudaFuncSetAttribute(m12_k, cudaFuncAttributeMaxDynamicSharedMemorySize, 49152);

    zero_k<<<128, 256>>>(out, c2w);              // 1st
    quad_k<<<977, 256>>>(mw, gm4);               // 2nd
    conv1_k<<<256, 256>>>(x, c1w, c1b);          // 3rd
    conv2_k<<<dim3(2, 256), 224, 59904>>>(c2b);  // 4th  <- profiled slot
    fc1_k<<<dim3(4, 2, 98), 256>>>(f1w);
    fc23_k<<<256, 128, 90624>>>(f1b, f2w, f2b, f3w, f3b);
    prep_k<<<1, 256>>>(cen, out);
    m12_k<<<10, 256, 49152>>>(mw, gm1, gm2, out);
    p3_k<<<77, 256, 49152>>>(mw, gm3, out);
    p4a_k<<<dim3(190, 10), 256, 65536>>>();
    p4b_k<<<977, 256>>>(out);
}

// round 11
// speedup vs baseline: 1.0694x; 1.0694x over previous
#include <cuda_runtime.h>
#include <math.h>
#include <stdint.h>

typedef unsigned long long u64;

// ---------------- scratch (static device globals; no allocation) -------------
__device__ float g_h1[256 * 32 * 30 * 30];   // conv1 output (relu'd)
__device__ float g_w2t[64 * 32 * 9];         // conv2 weights transposed [c][k][oc]
__device__ float g_h3[256 * 12544];          // conv2+pool output, flattened
__device__ float g_fc1[256 * 128];           // fc1 raw accumulator (pre-bias)
__device__ float g_z[256 * 48];              // backbone output
__device__ float g_dsel[256 * 48];           // class-sorted diffs (z - center[cls])
__device__ float g_cwn[10];                  // class weight / 256
__device__ int   g_seg[11];                  // class segment offsets into g_dsel

#define NPAIR 1176            // 48*49/2
#define NTRI  19600           // C(50,3)
#define NQUAD 249900          // C(51,4)
#define TRILEN 692076         // 1176*1177/2

__device__ float g_C[10 * TRILEN];           // per-class pair-pair products
__device__ int   g_qtri[NQUAD];
__device__ float g_qw[NQUAD];
__device__ float g_qt4[NQUAD];
__device__ unsigned short g_pij[NPAIR];

// ---------------- helpers ----------------------------------------------------
__device__ __forceinline__ float sgn_of(float m) { return (m < 0.f) ? -1.f : 1.f; }

__device__ __forceinline__ float sqapx(float x) {
    float y; asm("sqrt.approx.f32 %0, %1;" : "=f"(y) : "f"(x)); return y;
}
__device__ __forceinline__ float lg2apx(float x) {
    float y; asm("lg2.approx.f32 %0, %1;" : "=f"(y) : "f"(x)); return y;
}
__device__ __forceinline__ float ex2apx(float x) {
    float y; asm("ex2.approx.f32 %0, %1;" : "=f"(y) : "f"(x)); return y;
}
__device__ __forceinline__ float sr2a(float m) {
    return sgn_of(m) * (sqapx(fabsf(m) + 0.25f) - 0.5f);
}
__device__ __forceinline__ float sr3a(float m) {
    float x = fabsf(m) + 0.19245008973f;
    float r = ex2apx(lg2apx(x) * 0.3333333333f);
    return sgn_of(m) * (r - 0.57735026919f);
}
__device__ __forceinline__ float sr4a(float m) {
    return sgn_of(m) * (sqapx(sqapx(fabsf(m) + 0.15749013123f)) - 0.62996052494f);
}

__device__ __forceinline__ void decode_pair(int pi, int& i, int& j) {
    int ii = 0, rem = pi;
    while (rem >= 48 - ii) { rem -= 48 - ii; ii++; }
    i = ii; j = ii + rem;
}
__device__ __forceinline__ int pidx(int i, int j) {   // i<=j
    return i * 48 - (i * (i - 1)) / 2 + (j - i);
}

__device__ __forceinline__ float block_reduce_256(float v, float* red) {
    int tid = threadIdx.x;
    red[tid] = v; __syncthreads();
    for (int s = 128; s > 0; s >>= 1) {
        if (tid < s) red[tid] += red[tid + s];
        __syncthreads();
    }
    return red[0];
}

__device__ __forceinline__ u64 pk2(float lo, float hi) {
    u64 r; asm("mov.b64 %0, {%1, %2};" : "=l"(r) : "f"(lo), "f"(hi)); return r;
}
__device__ __forceinline__ void upk2(float& lo, float& hi, u64 v) {
    asm("mov.b64 {%0, %1}, %2;" : "=f"(lo), "=f"(hi) : "l"(v));
}
#define FMA2(d, a, b) asm("fma.rn.f32x2 %0, %1, %2, %0;" : "+l"(d) : "l"(a), "l"(b))

// ---------------- 0a: zero + w2 transpose + pair table -----------------------
__global__ void zero_k(float* __restrict__ out, const float* __restrict__ w2) {
    int i = blockIdx.x * 256 + threadIdx.x;
    if (i < 256 * 128) g_fc1[i] = 0.f;
    if (i < 4) out[2560 + i] = 0.f;
    if (i < 18432) {
        // dst [(c*9+k)*64 + oc] = src [oc*288 + c*9 + k]
        int oc = i / 288, rem = i - oc * 288;
        g_w2t[rem * 64 + oc] = w2[i];
    }
    if (i < NPAIR) {
        int a, b; decode_pair(i, a, b);
        g_pij[i] = (unsigned short)((a << 8) | b);
    }
}

// ---------------- 0b: quad list ----------------------------------------------
__global__ void quad_k(const float* __restrict__ mw, const float* __restrict__ gm4) {
    int e = blockIdx.x * 256 + threadIdx.x;
    if (e >= NQUAD) return;
    int r = e, a = 0, b = 0, c = 0, d;
    for (a = 0; a < 48; a++) { int n = 50 - a; int cnt = n * (n - 1) * (n - 2) / 6; if (r < cnt) break; r -= cnt; }
    for (b = a; b < 48; b++) { int n = 49 - b; int cnt = n * (n - 1) / 2; if (r < cnt) break; r -= cnt; }
    for (c = b; c < 48; c++) { int cnt = 48 - c; if (r < cnt) break; r -= cnt; }
    d = c + r;
    bool ab = (a == b), bc = (b == c), cd = (c == d);
    int perm;
    if (ab && bc && cd) perm = 1;
    else if ((ab && bc) || (bc && cd)) perm = 4;
    else if (ab && cd) perm = 6;
    else if (ab || bc || cd) perm = 12;
    else perm = 24;
    g_qw[e] = 0.25f * (float)perm * (mw[a] + mw[b] + mw[c] + mw[d]);
    int p = pidx(a, b), q = pidx(c, d);
    g_qtri[e] = p * 1176 - (p * (p - 1)) / 2 + (q - p);
    g_qt4[e] = sr4a(gm4[(((a * 48 + b) * 48) + c) * 48 + d]);
}

// ---------------- 1: conv1 (3->32, 3x3 valid, relu), sliding 3-col window ----
__global__ __launch_bounds__(256) void conv1_k(const float* __restrict__ x,
                                               const float* __restrict__ w,
                                               const float* __restrict__ bias) {
    __shared__ float xs[3 * 32 * 32];
    __shared__ float ws[32 * 27];
    __shared__ float bs[32];
    int b = blockIdx.x, tid = threadIdx.x;
    for (int i = tid; i < 3072; i += 256) xs[i] = x[b * 3072 + i];
    for (int i = tid; i < 864; i += 256) ws[i] = w[i];
    if (tid < 32) bs[tid] = bias[tid];
    __syncthreads();

    int oc = tid >> 3, ys = tid & 7;
    float wr[3][3][3];
#pragma unroll
    for (int c = 0; c < 3; c++)
#pragma unroll
        for (int ky = 0; ky < 3; ky++)
#pragma unroll
            for (int kx = 0; kx < 3; kx++)
                wr[c][ky][kx] = ws[oc * 27 + c * 9 + ky * 3 + kx];
    float bv = bs[oc];

    for (int y = ys; y < 30; y += 8) {
        float win[3][3][3];
#pragma unroll
        for (int c = 0; c < 3; c++)
#pragma unroll
            for (int ky = 0; ky < 3; ky++) {
                win[c][ky][0] = xs[c * 1024 + (y + ky) * 32 + 0];
                win[c][ky][1] = xs[c * 1024 + (y + ky) * 32 + 1];
            }
        float* orow = &g_h1[((b * 32 + oc) * 30 + y) * 30];
#pragma unroll
        for (int xc = 0; xc < 30; xc++) {
            int s2 = (xc + 2) % 3;
#pragma unroll
            for (int c = 0; c < 3; c++)
#pragma unroll
                for (int ky = 0; ky < 3; ky++)
                    win[c][ky][s2] = xs[c * 1024 + (y + ky) * 32 + xc + 2];
            float acc = bv;
#pragma unroll
            for (int c = 0; c < 3; c++)
#pragma unroll
                for (int ky = 0; ky < 3; ky++)
#pragma unroll
                    for (int kx = 0; kx < 3; kx++)
                        acc = fmaf(win[c][ky][(xc + kx) % 3], wr[c][ky][kx], acc);
            orow[xc] = fmaxf(acc, 0.f);
        }
    }
}

// ---------------- 2: conv2 + bias + relu + maxpool; oc-pair f32x2, 2 pooled --
// cols per thread, all 64 oc per block. grid (256 images), 224 threads =
// 2 prh x 7 colpairs x 16 ocq (4 oc each). Weights amortized over 2x positions.
__global__ __launch_bounds__(224, 2) void conv2_k(const float* __restrict__ bias) {
    extern __shared__ float sm[];
    float* wsh = sm;            // 18432 floats, [c][k][oc64] (== g_w2t layout)
    float* insh = sm + 18432;   // 32c x 6r x 30 = 5760 floats
    __shared__ float bs[64];
    int b = blockIdx.x, tid = threadIdx.x;

    {   // stage all weights (contiguous)
        float4* wd = (float4*)wsh;
        const float4* wsrc = (const float4*)g_w2t;
        for (int i = tid; i < 4608; i += 224) wd[i] = wsrc[i];
        if (tid < 64) bs[tid] = bias[tid];
    }

    int prh = tid / 112, rem = tid % 112, cp = rem / 16, ocq = rem & 15;

    for (int it = 0; it < 7; it++) {
        __syncthreads();
        for (int i = tid; i < 5760; i += 224) {
            int c = i / 180, r2 = i - c * 180;
            int r = r2 / 30, cc = r2 - r * 30;
            insh[i] = g_h1[((b * 32 + c) * 30 + 4 * it + r) * 30 + cc];
        }
        __syncthreads();

        u64 acc2[2][2][4];   // [oc pair][pooled col][conv pos dy*2+dx]
#pragma unroll
        for (int p2 = 0; p2 < 2; p2++)
#pragma unroll
            for (int pc = 0; pc < 2; pc++)
#pragma unroll
                for (int p = 0; p < 4; p++) acc2[p2][pc][p] = 0ull;

        for (int c = 0; c < 32; c++) {
            const float* ip = insh + c * 180 + prh * 60 + cp * 4;
            u64 wdup[4][6];   // 4 rows x 6 cols window, lane-duplicated
#pragma unroll
            for (int rr = 0; rr < 4; rr++) {
                float2 v0 = *(const float2*)&ip[rr * 30];
                float2 v1 = *(const float2*)&ip[rr * 30 + 2];
                float2 v2 = *(const float2*)&ip[rr * 30 + 4];
                wdup[rr][0] = pk2(v0.x, v0.x);
                wdup[rr][1] = pk2(v0.y, v0.y);
                wdup[rr][2] = pk2(v1.x, v1.x);
                wdup[rr][3] = pk2(v1.y, v1.y);
                wdup[rr][4] = pk2(v2.x, v2.x);
                wdup[rr][5] = pk2(v2.y, v2.y);
            }
#pragma unroll
            for (int kk = 0; kk < 9; kk++) {
                ulonglong2 wp = *(const ulonglong2*)&wsh[(c * 9 + kk) * 64 + ocq * 4];
                int ky = kk / 3, kx = kk - ky * 3;
#pragma unroll
                for (int pc = 0; pc < 2; pc++)
#pragma unroll
                    for (int dy = 0; dy < 2; dy++)
#pragma unroll
                        for (int dx = 0; dx < 2; dx++) {
                            u64 iv = wdup[dy + ky][dx + kx + 2 * pc];
                            FMA2(acc2[0][pc][dy * 2 + dx], wp.x, iv);
                            FMA2(acc2[1][pc][dy * 2 + dx], wp.y, iv);
                        }
            }
        }

        int pr = 2 * it + prh;
#pragma unroll
        for (int p2 = 0; p2 < 2; p2++)
#pragma unroll
            for (int pc = 0; pc < 2; pc++) {
                float l0, h0, l1, h1, l2, h2, l3, h3;
                upk2(l0, h0, acc2[p2][pc][0]); upk2(l1, h1, acc2[p2][pc][1]);
                upk2(l2, h2, acc2[p2][pc][2]); upk2(l3, h3, acc2[p2][pc][3]);
                float mlo = fmaxf(fmaxf(l0, l1), fmaxf(l2, l3));
                float mhi = fmaxf(fmaxf(h0, h1), fmaxf(h2, h3));
                int oc = ocq * 4 + p2 * 2;
                int colg = cp * 2 + pc;
                g_h3[b * 12544 + oc * 196 + pr * 14 + colg] = fmaxf(mlo + bs[oc], 0.f);
                g_h3[b * 12544 + (oc + 1) * 196 + pr * 14 + colg] = fmaxf(mhi + bs[oc + 1], 0.f);
            }
    }
}

// ---------------- 3: fc1 GEMM split-K (proven best: 4x4, BN=64, 56 splits) ---
__global__ void fc1_k(const float* __restrict__ w1) {
    __shared__ __align__(16) float As[32][64];
    __shared__ __align__(16) float Ws[32][64];
    int mt = blockIdx.x, nt = blockIdx.y, s = blockIdx.z, tid = threadIdx.x;
    int m0 = mt * 64, n0 = nt * 64;
    float acc[4][4];
#pragma unroll
    for (int u = 0; u < 4; u++)
#pragma unroll
        for (int v = 0; v < 4; v++) acc[u][v] = 0.f;

    int row = tid / 8, kc = (tid % 8) * 4;
    int tr = tid / 16, tc = tid % 16;

    for (int kt = 0; kt < 7; kt++) {
        int k0 = s * 224 + kt * 32;
#pragma unroll
        for (int h = 0; h < 2; h++) {
            float4 va = *(const float4*)&g_h3[(size_t)(m0 + row + 32 * h) * 12544 + k0 + kc];
            As[kc + 0][row + 32 * h] = va.x; As[kc + 1][row + 32 * h] = va.y;
            As[kc + 2][row + 32 * h] = va.z; As[kc + 3][row + 32 * h] = va.w;
            float4 vw = *(const float4*)&w1[(size_t)(n0 + row + 32 * h) * 12544 + k0 + kc];
            Ws[kc + 0][row + 32 * h] = vw.x; Ws[kc + 1][row + 32 * h] = vw.y;
            Ws[kc + 2][row + 32 * h] = vw.z; Ws[kc + 3][row + 32 * h] = vw.w;
        }
        __syncthreads();
#pragma unroll
        for (int kk = 0; kk < 32; kk++) {
            float4 a = *(const float4*)&As[kk][tr * 4];
            float4 wv = *(const float4*)&Ws[kk][tc * 4];
            float av[4] = {a.x, a.y, a.z, a.w};
            float wvv[4] = {wv.x, wv.y, wv.z, wv.w};
#pragma unroll
            for (int u = 0; u < 4; u++)
#pragma unroll
                for (int v = 0; v < 4; v++) acc[u][v] = fmaf(av[u], wvv[v], acc[u][v]);
        }
        __syncthreads();
    }
#pragma unroll
    for (int u = 0; u < 4; u++)
#pragma unroll
        for (int v = 0; v < 4; v++)
            atomicAdd(&g_fc1[(m0 + tr * 4 + u) * 128 + n0 + tc * 4 + v], acc[u][v]);
}

// ---------------- 4: bias+relu, fc2 (relu), fc3 -> z; smem-staged weights ----
__global__ void fc23_k(const float* __restrict__ b1, const float* __restrict__ w2,
                       const float* __restrict__ b2, const float* __restrict__ w3,
                       const float* __restrict__ b3) {
    extern __shared__ float smw[];
    float* w2s = smw;            // [k][o] pitch 129
    float* w3s = smw + 16512;    // [k][o] pitch 48
    __shared__ float s1[128], s2[128];
    int b = blockIdx.x, tid = threadIdx.x;

    for (int i4 = tid; i4 < 4096; i4 += 128) {
        float4 v = ((const float4*)w2)[i4];
        int o = (i4 * 4) / 128, k = (i4 * 4) % 128;
        w2s[(k + 0) * 129 + o] = v.x;
        w2s[(k + 1) * 129 + o] = v.y;
        w2s[(k + 2) * 129 + o] = v.z;
        w2s[(k + 3) * 129 + o] = v.w;
    }
    for (int i4 = tid; i4 < 1536; i4 += 128) {
        float4 v = ((const float4*)w3)[i4];
        int o = (i4 * 4) / 128, k = (i4 * 4) % 128;
        w3s[(k + 0) * 48 + o] = v.x;
        w3s[(k + 1) * 48 + o] = v.y;
        w3s[(k + 2) * 48 + o] = v.z;
        w3s[(k + 3) * 48 + o] = v.w;
    }
    s1[tid] = fmaxf(g_fc1[b * 128 + tid] + b1[tid], 0.f);
    __syncthreads();

    float acc = b2[tid];
    for (int k = 0; k < 128; k++) acc = fmaf(w2s[k * 129 + tid], s1[k], acc);
    s2[tid] = fmaxf(acc, 0.f);
    __syncthreads();
    if (tid < 48) {
        float a = b3[tid];
        for (int k = 0; k < 128; k++) a = fmaf(w3s[k * 48 + tid], s2[k], a);
        g_z[b * 48 + tid] = a;
    }
}

// ---------------- 5: distances, log-softmax, argmin, class sort --------------
__global__ void prep_k(const float* __restrict__ centers, float* __restrict__ out) {
    __shared__ float cs[480];
    __shared__ int counts[10], segs[11], cursor[10];
    int tid = threadIdx.x;
    for (int i = tid; i < 480; i += 256) cs[i] = centers[i];
    if (tid < 10) { counts[tid] = 0; cursor[tid] = 0; }
    __syncthreads();

    float zr[48];
#pragma unroll
    for (int i = 0; i < 48; i++) zr[i] = g_z[tid * 48 + i];

    float dist[10];
    int best = 0; float bd = 3.4e38f;
#pragma unroll
    for (int c = 0; c < 10; c++) {
        float d = 0.f;
#pragma unroll
        for (int i = 0; i < 48; i++) {
            float t = zr[i] - cs[c * 48 + i];
            d = fmaf(t, t, d);
        }
        dist[c] = d;
        if (d < bd) { bd = d; best = c; }
    }
    float mx = -3.4e38f;
#pragma unroll
    for (int c = 0; c < 10; c++) mx = fmaxf(mx, -0.5f * dist[c]);
    float se = 0.f;
#pragma unroll
    for (int c = 0; c < 10; c++) se += expf(-0.5f * dist[c] - mx);
    float lse = logf(se);
    float lclip = logf(1e-8f);
#pragma unroll
    for (int c = 0; c < 10; c++)
        out[tid * 10 + c] = fmaxf(-0.5f * dist[c] - mx - lse, lclip);

    atomicAdd(&counts[best], 1);
    __syncthreads();
    if (tid == 0) {
        segs[0] = 0;
        for (int c = 0; c < 10; c++) segs[c + 1] = segs[c] + counts[c];
    }
    __syncthreads();
    int pos = segs[best] + atomicAdd(&cursor[best], 1);
#pragma unroll
    for (int i = 0; i < 48; i++) g_dsel[pos * 48 + i] = zr[i] - cs[best * 48 + i];
    if (tid < 10) g_cwn[tid] = (float)counts[tid] * (1.f / 256.f);
    if (tid < 11) g_seg[tid] = segs[tid];
}

// ---------------- 6: p1 + p2 (per class, segment staged in smem) -------------
__global__ void m12_k(const float* __restrict__ mw, const float* __restrict__ gm1,
                      const float* __restrict__ gm2, float* __restrict__ out) {
    extern __shared__ float dss[];   // seg x 48
    __shared__ float red[256];
    int c = blockIdx.x, tid = threadIdx.x;
    int s0 = g_seg[c], s1 = g_seg[c + 1];
    int rows = s1 - s0;
    float cwf = (float)rows;
    float denom = cwf + 1e-7f;
    float cwn = cwf * (1.f / 256.f);

    for (int i = tid; i < rows * 12; i += 256)
        ((float4*)dss)[i] = ((const float4*)(g_dsel + s0 * 48))[i];
    __syncthreads();

    if (tid < 48) {
        float s = 0.f;
        for (int t = 0; t < rows; t++) s += dss[t * 48 + tid];
        float m1 = s / denom;
        float d = m1 - gm1[tid];
        atomicAdd(&out[2560], cwn * mw[tid] * d * d);
    }
    float part = 0.f;
    for (int e = tid; e < 2304; e += 256) {
        int i = e / 48, j = e % 48;
        float s = 0.f;
        for (int t = 0; t < rows; t++) s = fmaf(dss[t * 48 + i], dss[t * 48 + j], s);
        float v = sr2a(s / denom) - sr2a(gm2[e]);
        part += cwn * mw[j] * v * v;
    }
    float tot = block_reduce_256(part, red);
    if (tid == 0) atomicAdd(&out[2561], tot);
}

// ---------------- 7: p3 via sorted triples (full symmetry) -------------------
__global__ void p3_k(const float* __restrict__ mw, const float* __restrict__ gm3,
                     float* __restrict__ out) {
    extern __shared__ float ds[];   // 256*48
    __shared__ float cwnS[10];
    __shared__ int segS[11];
    __shared__ float red[256];
    int tid = threadIdx.x;
    for (int i = tid; i < 3072; i += 256) ((float4*)ds)[i] = ((const float4*)g_dsel)[i];
    if (tid < 10) cwnS[tid] = g_cwn[tid];
    if (tid < 11) segS[tid] = g_seg[tid];
    __syncthreads();

    int e = blockIdx.x * 256 + tid;
    float part = 0.f;
    if (e < NTRI) {
        int r = e, a = 0, b = 0, c3;
        for (a = 0; a < 48; a++) { int n = 49 - a; int cnt = n * (n - 1) / 2; if (r < cnt) break; r -= cnt; }
        for (b = a; b < 48; b++) { int cnt = 48 - b; if (r < cnt) break; r -= cnt; }
        c3 = b + r;
        bool ab = (a == b), bc = (b == c3);
        int perm = (ab && bc) ? 1 : ((ab || bc) ? 3 : 6);
        float wgt = (float)perm * (1.f / 3.f) * (mw[a] + mw[b] + mw[c3]);
        float t3 = sr3a(gm3[((a * 48 + b) * 48) + c3]);
        for (int c = 0; c < 10; c++) {
            float acc = 0.f;
            for (int t = segS[c]; t < segS[c + 1]; t++) {
                const float* d = ds + t * 48;
                acc = fmaf(d[a] * d[b], d[c3], acc);
            }
            float v = sr3a(acc) - t3;
            part += cwnS[c] * wgt * v * v;
        }
    }
    float tot = block_reduce_256(part, red);
    if (tid == 0) atomicAdd(&out[2562], tot);
}

// ---------------- 8a: pair-product GEMM C = P^T P per class ------------------
__global__ void p4a_k() {
    extern __shared__ float sm[];
    float* dsS = sm;             // up to 256*48
    float* As  = sm + 12288;     // 32*64
    float* Bs  = sm + 12288 + 2048;
    __shared__ unsigned short pijS[NPAIR];
    int tid = threadIdx.x;
    int c = blockIdx.y;
    int seg0 = g_seg[c], seg1 = g_seg[c + 1];
    int rows = seg1 - seg0;
    if (rows == 0) return;

    int tt = blockIdx.x, tp = 0;
    { int r = tt; for (tp = 0; tp < 19; tp++) { int n = 19 - tp; if (r < n) break; r -= n; } tt = r; }
    int tq = tp + tt;
    int p0 = tp * 64, q0 = tq * 64;

    for (int i = tid; i < NPAIR; i += 256) pijS[i] = g_pij[i];
    for (int i = tid; i < rows * 12; i += 256)
        ((float4*)dsS)[i] = ((const float4*)(g_dsel + seg0 * 48))[i];
    __syncthreads();

    int tr = tid >> 4, tc = tid & 15;
    float acc[4][4];
#pragma unroll
    for (int u = 0; u < 4; u++)
#pragma unroll
        for (int v = 0; v < 4; v++) acc[u][v] = 0.f;

    for (int tbase = 0; tbase < rows; tbase += 32) {
        for (int s = tid; s < 4096; s += 256) {
            int mtx = s >> 11, ss = s & 2047;
            int kkk = ss >> 6, pp = ss & 63;
            int p = (mtx ? q0 : p0) + pp;
            float v = 0.f;
            int t = tbase + kkk;
            if (p < NPAIR && t < rows) {
                int ij = pijS[p];
                v = dsS[t * 48 + (ij >> 8)] * dsS[t * 48 + (ij & 255)];
            }
            (mtx ? Bs : As)[ss] = v;
        }
        __syncthreads();
#pragma unroll
        for (int kkk = 0; kkk < 32; kkk++) {
            float4 a = *(const float4*)&As[kkk * 64 + tr * 4];
            float4 bv = *(const float4*)&Bs[kkk * 64 + tc * 4];
            float av[4] = {a.x, a.y, a.z, a.w};
            float bvv[4] = {bv.x, bv.y, bv.z, bv.w};
#pragma unroll
            for (int u = 0; u < 4; u++)
#pragma unroll
                for (int v = 0; v < 4; v++) acc[u][v] = fmaf(av[u], bvv[v], acc[u][v]);
        }
        __syncthreads();
    }

    float* Cc = g_C + (size_t)c * TRILEN;
#pragma unroll
    for (int u = 0; u < 4; u++) {
        int p = p0 + tr * 4 + u;
        if (p >= NPAIR) continue;
        int rowoff = p * 1176 - (p * (p - 1)) / 2 - p;
#pragma unroll
        for (int v = 0; v < 4; v++) {
            int q = q0 + tc * 4 + v;
            if (q < NPAIR && p <= q) Cc[rowoff + q] = acc[u][v];
        }
    }
}

// ---------------- 8b: p4 reduce over sorted quads ----------------------------
__global__ void p4b_k(float* __restrict__ out) {
    __shared__ float red[256];
    __shared__ float cw[10];
    int tid = threadIdx.x;
    if (tid < 10) cw[tid] = g_cwn[tid];
    __syncthreads();
    int e = blockIdx.x * 256 + tid;
    float part = 0.f;
    if (e < NQUAD) {
        int tri = g_qtri[e];
        float w = g_qw[e], t4 = g_qt4[e];
#pragma unroll
        for (int c = 0; c < 10; c++) {
            float cc = cw[c];
            if (cc <= 0.f) continue;
            float v = sr4a(g_C[(size_t)c * TRILEN + tri]) - t4;
            part += cc * w * v * v;
        }
    }
    float tot = block_reduce_256(part, red);
    if (tid == 0) atomicAdd(&out[2563], tot);
}

// ---------------- launch -----------------------------------------------------
extern "C" void kernel_launch(void* const* d_in, const int* in_sizes, int n_in,
                              void* d_out, int out_size) {
    const float* x    = (const float*)d_in[0];
    const float* c1w  = (const float*)d_in[1];
    const float* c1b  = (const float*)d_in[2];
    const float* c2w  = (const float*)d_in[3];
    const float* c2b  = (const float*)d_in[4];
    const float* f1w  = (const float*)d_in[5];
    const float* f1b  = (const float*)d_in[6];
    const float* f2w  = (const float*)d_in[7];
    const float* f2b  = (const float*)d_in[8];
    const float* f3w  = (const float*)d_in[9];
    const float* f3b  = (const float*)d_in[10];
    const float* cen  = (const float*)d_in[11];
    const float* mw   = (const float*)d_in[12];
    const float* gm1  = (const float*)d_in[13];
    const float* gm2  = (const float*)d_in[14];
    const float* gm3  = (const float*)d_in[15];
    const float* gm4  = (const float*)d_in[16];
    float* out = (float*)d_out;

    cudaFuncSetAttribute(conv2_k, cudaFuncAttributeMaxDynamicSharedMemorySize, 96768);
    cudaFuncSetAttribute(fc23_k, cudaFuncAttributeMaxDynamicSharedMemorySize, 90624);
    cudaFuncSetAttribute(p4a_k, cudaFuncAttributeMaxDynamicSharedMemorySize, 65536);
    cudaFuncSetAttribute(p3_k, cudaFuncAttributeMaxDynamicSharedMemorySize, 49152);
    cudaFuncSetAttribute(m12_k, cudaFuncAttributeMaxDynamicSharedMemorySize, 49152);

    zero_k<<<128, 256>>>(out, c2w);              // 1st
    quad_k<<<977, 256>>>(mw, gm4);               // 2nd
    conv1_k<<<256, 256>>>(x, c1w, c1b);          // 3rd
    conv2_k<<<256, 224, 96768>>>(c2b);           // 4th  <- profiled slot
    fc1_k<<<dim3(4, 2, 56), 256>>>(f1w);
    fc23_k<<<256, 128, 90624>>>(f1b, f2w, f2b, f3w, f3b);
    prep_k<<<1, 256>>>(cen, out);
    m12_k<<<10, 256, 49152>>>(mw, gm1, gm2, out);
    p3_k<<<77, 256, 49152>>>(mw, gm3, out);
    p4a_k<<<dim3(190, 10), 256, 65536>>>();
    p4b_k<<<977, 256>>>(out);
}